// round 11
// baseline (speedup 1.0000x reference)
#include <cuda_runtime.h>
#include <cuda_fp16.h>

// ---------------------------------------------------------------------------
// LapImage: fused 4-level trilinear grid_sample (align_corners=True)
// Round 11 = R9 (198.7us passing base) + two mechanical levers from R10:
//   * sample processes 2 consecutive sorted points per thread
//   * unpermute processes 2 consecutive points per thread (uint2/float2 ops)
// Explicit zero_kernel reinstated (R10's zero-invariant trick dropped).
// Pipeline: zero -> repack_hist -> scan1(+cnt=0 kept out; zeroed by zero_kernel)
//           -> scan2 -> permute -> sample -> unpermute     (7 launches)
// ---------------------------------------------------------------------------

#define NPTS   (4 * 96 * 96 * 96)   // 3,538,944
#define PLANE  (96 * 96 * 96)       // 884,736
#define NVOX   2785280              // 32768 + 131072 + 524288 + 2097152
#define NBINS  262144               // 32 z * 256 y * 32 x-lines (lvl3)
#define NBLK   512

__device__ uint4    g_vol[NVOX];      // 44.6 MB pair-packed fp16 volumes (x-innermost)
__device__ unsigned g_hist[NBINS];
__device__ unsigned g_cnt[NBINS];     // permute-time per-bin counters
__device__ unsigned g_off1[NBINS];    // exclusive scan within 512-chunk
__device__ unsigned g_off2[NBLK];     // exclusive chunk offsets
__device__ uint4    g_sorted[NPTS];   // {gx,gy,gz,p} -> overwritten with {r,g,b,-}
__device__ unsigned g_inv[NPTS];      // original index p -> sorted position

// ---------------- spatial key: lvl3 cache-line granularity -----------------
__device__ __forceinline__ int point_key(float gx, float gy, float gz) {
    int z0 = min((int)((gz + 1.0f) * 15.5f), 30);
    int y3 = min((int)((gy + 1.0f) * 127.5f), 254);
    int x3 = min((int)((gx + 1.0f) * 127.5f), 254);
    return (z0 * 256 + y3) * 32 + (x3 >> 3);   // 8 pair-entries = 128B line
}

__global__ __launch_bounds__(256)
void zero_kernel() {
    int i = blockIdx.x * blockDim.x + threadIdx.x;
    if (i < NBINS) { g_hist[i] = 0u; g_cnt[i] = 0u; }
}

// ---------------- fused repack (i < NVOX) + histogram (i < NPTS) -----------
__global__ __launch_bounds__(256)
void repack_hist_kernel(const float* __restrict__ coords,
                        const float* __restrict__ i0, const float* __restrict__ i1,
                        const float* __restrict__ i2, const float* __restrict__ i3) {
    int i = blockIdx.x * blockDim.x + threadIdx.x;

    if (i < NVOX) {
        const float* __restrict__ src;
        int n, base;
        if (i < 32768)        { src = i0; n = 32768;   base = 0;      }
        else if (i < 163840)  { src = i1; n = 131072;  base = 32768;  }
        else if (i < 688128)  { src = i2; n = 524288;  base = 163840; }
        else                  { src = i3; n = 2097152; base = 688128; }

        int li = i - base;
        int j  = min(li + 1, n - 1);   // x+1 neighbor; row-crossing entry never sampled

        __half2 p0 = __halves2half2(__float2half_rn(src[li]),         __float2half_rn(src[n + li]));
        __half2 p1 = __halves2half2(__float2half_rn(src[2 * n + li]), __float2half_rn(src[j]));
        __half2 p2 = __halves2half2(__float2half_rn(src[n + j]),      __float2half_rn(src[2 * n + j]));
        uint4 v;
        v.x = *(unsigned int*)&p0;
        v.y = *(unsigned int*)&p1;
        v.z = *(unsigned int*)&p2;
        v.w = 0u;
        g_vol[i] = v;
    }

    if (i < NPTS) {
        atomicAdd(&g_hist[point_key(coords[3 * i], coords[3 * i + 1], coords[3 * i + 2])], 1u);
    }
}

__global__ __launch_bounds__(512)
void scan1_kernel() {
    __shared__ unsigned s[512];
    int t   = threadIdx.x;
    int idx = blockIdx.x * 512 + t;
    unsigned v = g_hist[idx];
    s[t] = v;
    __syncthreads();
#pragma unroll
    for (int d = 1; d < 512; d <<= 1) {
        unsigned add = (t >= d) ? s[t - d] : 0u;
        __syncthreads();
        s[t] += add;
        __syncthreads();
    }
    g_off1[idx] = s[t] - v;
    if (t == 511) g_off2[blockIdx.x] = s[t];
}

__global__ __launch_bounds__(512)
void scan2_kernel() {
    __shared__ unsigned s[512];
    int t = threadIdx.x;
    unsigned v = g_off2[t];
    s[t] = v;
    __syncthreads();
#pragma unroll
    for (int d = 1; d < 512; d <<= 1) {
        unsigned add = (t >= d) ? s[t - d] : 0u;
        __syncthreads();
        s[t] += add;
        __syncthreads();
    }
    g_off2[t] = s[t] - v;
}

__global__ __launch_bounds__(256)
void permute_kernel(const float* __restrict__ coords) {
    int p = blockIdx.x * blockDim.x + threadIdx.x;
    if (p >= NPTS) return;
    float gx = coords[3 * p + 0];
    float gy = coords[3 * p + 1];
    float gz = coords[3 * p + 2];
    int k = point_key(gx, gy, gz);
    unsigned rank = atomicAdd(&g_cnt[k], 1u);
    unsigned pos  = g_off1[k] + g_off2[k >> 9] + rank;
    uint4 r;
    r.x = __float_as_uint(gx);
    r.y = __float_as_uint(gy);
    r.z = __float_as_uint(gz);
    r.w = (unsigned)p;
    g_sorted[pos] = r;
    g_inv[p] = pos;
}

// ---------------- sampling: 2 consecutive sorted points per thread ---------
__device__ __forceinline__ void acc_pair(uint4 q, float w, float wx0, float wx1,
                                         float& ax, float& ay, float& az) {
    float2 f0 = __half22float2(*(__half2*)&q.x);   // c0(x0), c1(x0)
    float2 f1 = __half22float2(*(__half2*)&q.y);   // c2(x0), c0(x1)
    float2 f2 = __half22float2(*(__half2*)&q.z);   // c1(x1), c2(x1)
    ax = fmaf(w, fmaf(f0.x, wx0, f1.y * wx1), ax);
    ay = fmaf(w, fmaf(f0.y, wx0, f2.x * wx1), ay);
    az = fmaf(w, fmaf(f1.x, wx0, f2.y * wx1), az);
}

__global__ __launch_bounds__(256)
void sample_kernel() {
    int t = blockIdx.x * blockDim.x + threadIdx.x;
    if (t >= NPTS / 2) return;
    int i = 2 * t;

    float gx[2], gy[2], gz[2], ax[2], ay[2], az[2];
    float wz0[2], wz1[2];
    int   z0[2];

#pragma unroll
    for (int k = 0; k < 2; ++k) {
        uint4 rec = g_sorted[i + k];
        gx[k] = __uint_as_float(rec.x);
        gy[k] = __uint_as_float(rec.y);
        gz[k] = __uint_as_float(rec.z);
        float iz  = (gz[k] + 1.0f) * 15.5f;
        float z0f = floorf(iz);
        wz1[k] = iz - z0f;
        wz0[k] = 1.0f - wz1[k];
        z0[k]  = min((int)z0f, 30);
        ax[k] = ay[k] = az[k] = 0.0f;
    }

    const int offs[4] = {0, 32768, 163840, 688128};

#pragma unroll
    for (int lvl = 0; lvl < 4; ++lvl) {
        const int   HW = 32 << lvl;
        const float sc = 0.5f * (float)(HW - 1);
        const uint4* __restrict__ vol = g_vol + offs[lvl];

#pragma unroll
        for (int k = 0; k < 2; ++k) {
            float ix  = (gx[k] + 1.0f) * sc;
            float iy  = (gy[k] + 1.0f) * sc;
            float x0f = floorf(ix);
            float y0f = floorf(iy);
            float wx1 = ix - x0f, wx0 = 1.0f - wx1;
            float wy1 = iy - y0f, wy0 = 1.0f - wy1;
            int x0 = min((int)x0f, HW - 2);
            int y0 = min((int)y0f, HW - 2);
            int y1 = y0 + 1;

            int r00 = (z0[k] * HW + y0) * HW + x0;
            int r01 = (z0[k] * HW + y1) * HW + x0;
            int r10 = r00 + HW * HW;
            int r11 = r01 + HW * HW;

            uint4 q00 = __ldg(vol + r00);
            uint4 q01 = __ldg(vol + r01);
            uint4 q10 = __ldg(vol + r10);
            uint4 q11 = __ldg(vol + r11);

            acc_pair(q00, wz0[k] * wy0, wx0, wx1, ax[k], ay[k], az[k]);
            acc_pair(q01, wz0[k] * wy1, wx0, wx1, ax[k], ay[k], az[k]);
            acc_pair(q10, wz1[k] * wy0, wx0, wx1, ax[k], ay[k], az[k]);
            acc_pair(q11, wz1[k] * wy1, wx0, wx1, ax[k], ay[k], az[k]);
        }
    }

#pragma unroll
    for (int k = 0; k < 2; ++k) {
        uint4 res;
        res.x = __float_as_uint(ax[k]);
        res.y = __float_as_uint(ay[k]);
        res.z = __float_as_uint(az[k]);
        res.w = 0u;
        g_sorted[i + k] = res;       // coalesced in-place overwrite
    }
}

// ---------------- gather results back: 2 points per thread -----------------
__global__ __launch_bounds__(256)
void unpermute_kernel(float* __restrict__ out) {
    int t = blockIdx.x * blockDim.x + threadIdx.x;
    if (t >= NPTS / 2) return;
    int p = 2 * t;                              // p even; pair stays in one batch

    uint2 pos2 = *(const uint2*)&g_inv[p];      // coalesced 8B
    uint4 r0 = __ldg(&g_sorted[pos2.x]);        // scattered 16B gathers (L2-resident)
    uint4 r1 = __ldg(&g_sorted[pos2.y]);

    int b  = p / PLANE;
    int pl = p - b * PLANE;
    float* o = out + (size_t)b * (3 * PLANE) + pl;
    float2 c0 = make_float2(__uint_as_float(r0.x), __uint_as_float(r1.x));
    float2 c1 = make_float2(__uint_as_float(r0.y), __uint_as_float(r1.y));
    float2 c2 = make_float2(__uint_as_float(r0.z), __uint_as_float(r1.z));
    *(float2*)&o[0]         = c0;
    *(float2*)&o[PLANE]     = c1;
    *(float2*)&o[2 * PLANE] = c2;
}

extern "C" void kernel_launch(void* const* d_in, const int* in_sizes, int n_in,
                              void* d_out, int out_size) {
    const float* coords = (const float*)d_in[0];
    const float* img0   = (const float*)d_in[1];
    const float* img1   = (const float*)d_in[2];
    const float* img2   = (const float*)d_in[3];
    const float* img3   = (const float*)d_in[4];
    float* out = (float*)d_out;

    zero_kernel<<<NBINS / 256, 256>>>();
    repack_hist_kernel<<<(NPTS + 255) / 256, 256>>>(coords, img0, img1, img2, img3);
    scan1_kernel<<<NBLK, 512>>>();
    scan2_kernel<<<1, 512>>>();
    permute_kernel<<<NPTS / 256, 256>>>(coords);
    sample_kernel<<<NPTS / 2 / 256, 256>>>();
    unpermute_kernel<<<NPTS / 2 / 256, 256>>>(out);
}